// round 17
// baseline (speedup 1.0000x reference)
#include <cuda_runtime.h>
#include <cuda_bf16.h>
#include <math.h>
#include <stdint.h>

#define D 128
#define NMAX 20000
#define EMAX 640000
#define LN_EPS 1e-5f

// ---------------- device scratch (no allocs allowed) ----------------
__device__ float g_aggf[NMAX * D];     // segment-max result (0 for empty)
__device__ float g_h[NMAX * D];        // h after first LayerNorm
__device__ float g_xw[NMAX * D];       // x @ Wroot^T (computed on side stream)
__device__ int   g_cnt[NMAX];          // per-node degree counters
__device__ int   g_off[NMAX + 1];      // CSR offsets
__device__ int   g_bsum[64];           // per-scan-block sums
__device__ int   g_pos[EMAX];          // per-edge slot within its dst bucket
__device__ int   g_src[EMAX];          // CSR-ordered source ids
__device__ float g_w[EMAX];            // CSR-ordered edge weights
__device__ int   g_i64;                // 1 if edge_index buffer is int64

__device__ __forceinline__ float gelu_exact(float v) { return v * normcdff(v); }

// ---------------- K0: detect int64 + zero counters ----------------
__global__ void k_prep(const int* __restrict__ ei, int n) {
    int i = blockIdx.x * blockDim.x + threadIdx.x;
    if (i < n) g_cnt[i] = 0;
    if (blockIdx.x == 0) {
        __shared__ int bad;
        if (threadIdx.x == 0) bad = 0;
        __syncthreads();
        int any = 0;
        for (int j = threadIdx.x; j < 1024; j += blockDim.x)
            if (ei[2 * j + 1] != 0) any = 1;
        if (any) atomicOr(&bad, 1);
        __syncthreads();
        if (threadIdx.x == 0) g_i64 = (bad == 0) ? 1 : 0;
    }
}

__global__ void k_count(const int* __restrict__ ei, int e) {
    int i = blockIdx.x * blockDim.x + threadIdx.x;
    if (i >= e) return;
    int dst = g_i64 ? ei[2 * (e + i)] : ei[e + i];
    g_pos[i] = atomicAdd(&g_cnt[dst], 1);
}

// ---------------- parallel scan ----------------
__global__ void k_scan1(int n) {
    __shared__ int wsum[32];
    int i = blockIdx.x * 1024 + threadIdx.x;
    int lane = threadIdx.x & 31, wid = threadIdx.x >> 5;
    int v = (i < n) ? g_cnt[i] : 0;
    #pragma unroll
    for (int o = 16; o; o >>= 1) v += __shfl_xor_sync(0xffffffffu, v, o);
    if (lane == 0) wsum[wid] = v;
    __syncthreads();
    if (wid == 0) {
        int s = wsum[lane];
        #pragma unroll
        for (int o = 16; o; o >>= 1) s += __shfl_xor_sync(0xffffffffu, s, o);
        if (lane == 0) g_bsum[blockIdx.x] = s;
    }
}

__global__ void k_scan2(int n) {
    __shared__ int wsum[32];
    __shared__ int prefix_s;
    int tid = threadIdx.x, lane = tid & 31, wid = tid >> 5;
    int b = blockIdx.x;
    if (tid == 0) {
        int p = 0;
        for (int j = 0; j < b; j++) p += g_bsum[j];
        prefix_s = p;
    }
    int i = b * 1024 + tid;
    int v = (i < n) ? g_cnt[i] : 0;
    int s = v;
    #pragma unroll
    for (int o = 1; o < 32; o <<= 1) {
        int t = __shfl_up_sync(0xffffffffu, s, o);
        if (lane >= o) s += t;
    }
    if (lane == 31) wsum[wid] = s;
    __syncthreads();
    if (wid == 0) {
        int ws = wsum[lane];
        #pragma unroll
        for (int o = 1; o < 32; o <<= 1) {
            int t = __shfl_up_sync(0xffffffffu, ws, o);
            if (lane >= o) ws += t;
        }
        wsum[lane] = ws;
    }
    __syncthreads();
    int prefix = prefix_s;
    int excl = prefix + s - v + (wid > 0 ? wsum[wid - 1] : 0);
    if (i < n) g_off[i] = excl;
    if (b == gridDim.x - 1 && tid == 0) g_off[n] = prefix + wsum[31];
}

__global__ void k_place(const int* __restrict__ ei, const float* __restrict__ ew, int e) {
    int i = blockIdx.x * blockDim.x + threadIdx.x;
    if (i >= e) return;
    int src, dst;
    if (g_i64) { src = ei[2 * i]; dst = ei[2 * (e + i)]; }
    else       { src = ei[i];     dst = ei[e + i]; }
    int idx = g_off[dst] + g_pos[i];
    g_src[idx] = src;
    g_w[idx]   = ew[i];
}

// ---------------- per-node gather-max: one warp per node (node range) ----------------
__global__ void k_agg(const float* __restrict__ x, int node0, int node1) {
    int wp = threadIdx.x >> 5, lane = threadIdx.x & 31;
    int node = node0 + blockIdx.x * 8 + wp;
    if (node >= node1) return;
    int s0 = g_off[node], s1 = g_off[node + 1];
    const float4* x4 = (const float4*)x;
    float4 m = make_float4(-INFINITY, -INFINITY, -INFINITY, -INFINITY);
    int i = s0;
    for (; i + 3 < s1; i += 4) {
        int sa = g_src[i], sb = g_src[i + 1], sc = g_src[i + 2], sd = g_src[i + 3];
        float wa = g_w[i], wb = g_w[i + 1], wc = g_w[i + 2], wd = g_w[i + 3];
        float4 va = __ldcg(&x4[sa * 32 + lane]);
        float4 vb = __ldcg(&x4[sb * 32 + lane]);
        float4 vc = __ldcg(&x4[sc * 32 + lane]);
        float4 vd = __ldcg(&x4[sd * 32 + lane]);
        m.x = fmaxf(m.x, va.x * wa); m.y = fmaxf(m.y, va.y * wa);
        m.z = fmaxf(m.z, va.z * wa); m.w = fmaxf(m.w, va.w * wa);
        m.x = fmaxf(m.x, vb.x * wb); m.y = fmaxf(m.y, vb.y * wb);
        m.z = fmaxf(m.z, vb.z * wb); m.w = fmaxf(m.w, vb.w * wb);
        m.x = fmaxf(m.x, vc.x * wc); m.y = fmaxf(m.y, vc.y * wc);
        m.z = fmaxf(m.z, vc.z * wc); m.w = fmaxf(m.w, vc.w * wc);
        m.x = fmaxf(m.x, vd.x * wd); m.y = fmaxf(m.y, vd.y * wd);
        m.z = fmaxf(m.z, vd.z * wd); m.w = fmaxf(m.w, vd.w * wd);
    }
    for (; i < s1; i++) {
        int sa = g_src[i]; float wa = g_w[i];
        float4 va = __ldcg(&x4[sa * 32 + lane]);
        m.x = fmaxf(m.x, va.x * wa); m.y = fmaxf(m.y, va.y * wa);
        m.z = fmaxf(m.z, va.z * wa); m.w = fmaxf(m.w, va.w * wa);
    }
    if (s1 <= s0) m = make_float4(0.f, 0.f, 0.f, 0.f);
    ((float4*)g_aggf)[node * 32 + lane] = m;
}

// ================= HMMA (mma.sync bf16) GEMMs =================
// 64-row chunks, 128 threads (4 warps x 16-row band), 2 CTAs/SM.
#define BPITCH 272
#define WMAT_BYTES (128 * BPITCH)   // 34816
#define AMAT_BYTES (64 * BPITCH)    // 17408

#define SG_BIAS 0
#define SG_GAM  512
#define SG_BET  1024
#define SG_W1H  1536
#define SG_W1L  (SG_W1H + WMAT_BYTES)
#define SH_AHI  (SG_W1L + WMAT_BYTES)
#define SH_ALO  (SH_AHI + AMAT_BYTES)
#define SMEM_GEMM (SH_ALO + AMAT_BYTES)   // 105984

__device__ __forceinline__ void mma16816(float* c, uint32_t a0, uint32_t a1,
                                         uint32_t a2, uint32_t a3,
                                         uint32_t b0, uint32_t b1) {
    asm volatile("mma.sync.aligned.m16n8k16.row.col.f32.bf16.bf16.f32 "
        "{%0,%1,%2,%3}, {%4,%5,%6,%7}, {%8,%9}, {%0,%1,%2,%3};"
        : "+f"(c[0]), "+f"(c[1]), "+f"(c[2]), "+f"(c[3])
        : "r"(a0), "r"(a1), "r"(a2), "r"(a3), "r"(b0), "r"(b1));
}

// stage 128-row weight matrix with 128 threads
__device__ __forceinline__ void stage_w(char* dhi, char* dlo,
                                        const float* __restrict__ src, int tid) {
    #pragma unroll 4
    for (int p = tid; p < 128 * 64; p += 128) {
        int r = p >> 6, kp = p & 63;
        float2 v = ((const float2*)src)[r * 64 + kp];
        __nv_bfloat162 hi = __floats2bfloat162_rn(v.x, v.y);
        float rx = v.x - __bfloat162float(__low2bfloat16(hi));
        float ry = v.y - __bfloat162float(__high2bfloat16(hi));
        __nv_bfloat162 lo = __floats2bfloat162_rn(rx, ry);
        *(uint32_t*)(dhi + r * BPITCH + kp * 4) = *reinterpret_cast<uint32_t*>(&hi);
        *(uint32_t*)(dlo + r * BPITCH + kp * 4) = *reinterpret_cast<uint32_t*>(&lo);
    }
}

// stage 64-row A tile with 128 threads
__device__ __forceinline__ void stage_a(char* dhi, char* dlo,
                                        const float* __restrict__ src,
                                        int rows_valid, int tid) {
    #pragma unroll 4
    for (int p = tid; p < 64 * 64; p += 128) {
        int r = p >> 6, kp = p & 63;
        float2 v = (r < rows_valid) ? ((const float2*)src)[r * 64 + kp]
                                    : make_float2(0.f, 0.f);
        __nv_bfloat162 hi = __floats2bfloat162_rn(v.x, v.y);
        float rx = v.x - __bfloat162float(__low2bfloat16(hi));
        float ry = v.y - __bfloat162float(__high2bfloat16(hi));
        __nv_bfloat162 lo = __floats2bfloat162_rn(rx, ry);
        *(uint32_t*)(dhi + r * BPITCH + kp * 4) = *reinterpret_cast<uint32_t*>(&hi);
        *(uint32_t*)(dlo + r * BPITCH + kp * 4) = *reinterpret_cast<uint32_t*>(&lo);
    }
}

// One K=128 pass: c[16][4] += A(16-row band) * W^T, 3-term bf16 split.
__device__ __forceinline__ void mma_phase(float c[16][4],
                                          const char* ah_, const char* al_,
                                          const char* wh_, const char* wl_,
                                          int wband, int g, int tig) {
    const char* arh  = ah_ + (wband + g) * BPITCH;
    const char* arh8 = arh + 8 * BPITCH;
    const char* arl  = al_ + (wband + g) * BPITCH;
    const char* arl8 = arl + 8 * BPITCH;
    const char* wh = wh_ + g * BPITCH;
    const char* wl = wl_ + g * BPITCH;
    #pragma unroll 2
    for (int ks = 0; ks < 8; ks++) {
        int kb = ks * 32 + tig * 4;
        uint32_t ah0 = *(const uint32_t*)(arh  + kb);
        uint32_t ah1 = *(const uint32_t*)(arh8 + kb);
        uint32_t ah2 = *(const uint32_t*)(arh  + kb + 16);
        uint32_t ah3 = *(const uint32_t*)(arh8 + kb + 16);
        uint32_t al0 = *(const uint32_t*)(arl  + kb);
        uint32_t al1 = *(const uint32_t*)(arl8 + kb);
        uint32_t al2 = *(const uint32_t*)(arl  + kb + 16);
        uint32_t al3 = *(const uint32_t*)(arl8 + kb + 16);
        #pragma unroll
        for (int nt = 0; nt < 16; nt++) {
            const char* ph = wh + nt * 8 * BPITCH + kb;
            const char* pl = wl + nt * 8 * BPITCH + kb;
            uint32_t bh0 = *(const uint32_t*)(ph);
            uint32_t bh1 = *(const uint32_t*)(ph + 16);
            uint32_t bl0 = *(const uint32_t*)(pl);
            uint32_t bl1 = *(const uint32_t*)(pl + 16);
            mma16816(c[nt], ah0, ah1, ah2, ah3, bh0, bh1);
            mma16816(c[nt], ah0, ah1, ah2, ah3, bl0, bl1);
            mma16816(c[nt], al0, al1, al2, al3, bh0, bh1);
        }
    }
}

// epilogue: gelu(c+bias)+skip, LN over row, store.
__device__ __forceinline__ void epilogue(float c[16][4], const char* smem,
                                         const float* __restrict__ skip,
                                         float* __restrict__ dst,
                                         int row0, int wband, int g, int tig, int n) {
    const float* sb  = (const float*)(smem + SG_BIAS);
    const float* sg_ = (const float*)(smem + SG_GAM);
    const float* sbt = (const float*)(smem + SG_BET);
    int rA = row0 + wband + g;
    int rB = rA + 8;
    float sA = 0.f, qA = 0.f, sB = 0.f, qB = 0.f;
    #pragma unroll
    for (int nt = 0; nt < 16; nt++) {
        int col = nt * 8 + tig * 2;
        float2 xa = (rA < n) ? *(const float2*)(skip + (size_t)rA * 128 + col)
                             : make_float2(0.f, 0.f);
        float2 xb = (rB < n) ? *(const float2*)(skip + (size_t)rB * 128 + col)
                             : make_float2(0.f, 0.f);
        c[nt][0] = gelu_exact(c[nt][0] + sb[col])     + xa.x;
        c[nt][1] = gelu_exact(c[nt][1] + sb[col + 1]) + xa.y;
        c[nt][2] = gelu_exact(c[nt][2] + sb[col])     + xb.x;
        c[nt][3] = gelu_exact(c[nt][3] + sb[col + 1]) + xb.y;
        sA += c[nt][0] + c[nt][1]; qA += c[nt][0] * c[nt][0] + c[nt][1] * c[nt][1];
        sB += c[nt][2] + c[nt][3]; qB += c[nt][2] * c[nt][2] + c[nt][3] * c[nt][3];
    }
    #pragma unroll
    for (int o = 1; o <= 2; o <<= 1) {
        sA += __shfl_xor_sync(0xffffffffu, sA, o);
        qA += __shfl_xor_sync(0xffffffffu, qA, o);
        sB += __shfl_xor_sync(0xffffffffu, sB, o);
        qB += __shfl_xor_sync(0xffffffffu, qB, o);
    }
    float muA = sA * (1.f / D);
    float rsA = rsqrtf(fmaxf(qA * (1.f / D) - muA * muA, 0.f) + LN_EPS);
    float muB = sB * (1.f / D);
    float rsB = rsqrtf(fmaxf(qB * (1.f / D) - muB * muB, 0.f) + LN_EPS);
    #pragma unroll
    for (int nt = 0; nt < 16; nt++) {
        int col = nt * 8 + tig * 2;
        if (rA < n) {
            float2 y;
            y.x = (c[nt][0] - muA) * rsA * sg_[col]     + sbt[col];
            y.y = (c[nt][1] - muA) * rsA * sg_[col + 1] + sbt[col + 1];
            *(float2*)(dst + (size_t)rA * 128 + col) = y;
        }
        if (rB < n) {
            float2 y;
            y.x = (c[nt][2] - muB) * rsB * sg_[col]     + sbt[col];
            y.y = (c[nt][3] - muB) * rsB * sg_[col + 1] + sbt[col + 1];
            *(float2*)(dst + (size_t)rB * 128 + col) = y;
        }
    }
}

// ---- side-stream kernel: g_xw = x @ Wroot^T (raw fp32), one 64-row chunk/CTA ----
__global__ void __launch_bounds__(128, 2)
k_xroot(const float* __restrict__ x, const float* __restrict__ Wroot, int n) {
    extern __shared__ char smem[];
    int tid = threadIdx.x, lane = tid & 31, wp = tid >> 5;
    int g = lane >> 2, tig = lane & 3, wband = wp * 16;
    int row0 = blockIdx.x * 64;
    int rv = n - row0; if (rv > 64) rv = 64;

    stage_w(smem + SG_W1H, smem + SG_W1L, Wroot, tid);
    __syncthreads();

    float c[16][4];
    #pragma unroll
    for (int t = 0; t < 16; t++)
        c[t][0] = c[t][1] = c[t][2] = c[t][3] = 0.f;

    stage_a(smem + SH_AHI, smem + SH_ALO, x + (size_t)row0 * 128, rv, tid);
    __syncthreads();
    mma_phase(c, smem + SH_AHI, smem + SH_ALO, smem + SG_W1H, smem + SG_W1L,
              wband, g, tig);

    int rA = row0 + wband + g, rB = rA + 8;
    #pragma unroll
    for (int nt = 0; nt < 16; nt++) {
        int col = nt * 8 + tig * 2;
        if (rA < n) *(float2*)(g_xw + (size_t)rA * 128 + col)
                    = make_float2(c[nt][0], c[nt][1]);
        if (rB < n) *(float2*)(g_xw + (size_t)rB * 128 + col)
                    = make_float2(c[nt][2], c[nt][3]);
    }
}

// h = LN( gelu(agg@Wrel^T + b + xw) + x )  over rows [row_base, row_base+64*grid)
__global__ void __launch_bounds__(128, 2)
k_gemm1_mma(const float* __restrict__ x, const float* __restrict__ Wrel,
            const float* __restrict__ brel,
            const float* __restrict__ gamma, const float* __restrict__ beta,
            int row_base, int n) {
    extern __shared__ char smem[];
    int tid = threadIdx.x, lane = tid & 31, wp = tid >> 5;
    int g = lane >> 2, tig = lane & 3, wband = wp * 16;
    int row0 = row_base + blockIdx.x * 64;
    int rv = n - row0; if (rv > 64) rv = 64;
    if (rv <= 0) return;

    stage_w(smem + SG_W1H, smem + SG_W1L, Wrel, tid);
    if (tid < 128) {
        ((float*)(smem + SG_BIAS))[tid] = brel[tid];
        ((float*)(smem + SG_GAM))[tid]  = gamma[tid];
        ((float*)(smem + SG_BET))[tid]  = beta[tid];
    }
    __syncthreads();

    float c[16][4];
    #pragma unroll
    for (int t = 0; t < 16; t++)
        c[t][0] = c[t][1] = c[t][2] = c[t][3] = 0.f;

    stage_a(smem + SH_AHI, smem + SH_ALO, g_aggf + (size_t)row0 * 128, rv, tid);
    __syncthreads();
    mma_phase(c, smem + SH_AHI, smem + SH_ALO, smem + SG_W1H, smem + SG_W1L,
              wband, g, tig);

    int rA = row0 + wband + g, rB = rA + 8;
    #pragma unroll
    for (int nt = 0; nt < 16; nt++) {
        int col = nt * 8 + tig * 2;
        float2 wa = (rA < n) ? *(const float2*)(g_xw + (size_t)rA * 128 + col)
                             : make_float2(0.f, 0.f);
        float2 wb = (rB < n) ? *(const float2*)(g_xw + (size_t)rB * 128 + col)
                             : make_float2(0.f, 0.f);
        c[nt][0] += wa.x; c[nt][1] += wa.y;
        c[nt][2] += wb.x; c[nt][3] += wb.y;
    }
    epilogue(c, smem, x, g_h, row0, wband, g, tig, n);
}

// out = LN( gelu(h@linW^T + lb) + h )
__global__ void __launch_bounds__(128, 2)
k_gemm2_mma(const float* __restrict__ lw, const float* __restrict__ lb,
            const float* __restrict__ gamma, const float* __restrict__ beta,
            float* __restrict__ out, int n) {
    extern __shared__ char smem[];
    int tid = threadIdx.x, lane = tid & 31, wp = tid >> 5;
    int g = lane >> 2, tig = lane & 3, wband = wp * 16;
    int row0 = blockIdx.x * 64;
    int rv = n - row0; if (rv > 64) rv = 64;
    if (rv <= 0) return;

    stage_w(smem + SG_W1H, smem + SG_W1L, lw, tid);
    if (tid < 128) {
        ((float*)(smem + SG_BIAS))[tid] = lb[tid];
        ((float*)(smem + SG_GAM))[tid]  = gamma[tid];
        ((float*)(smem + SG_BET))[tid]  = beta[tid];
    }
    __syncthreads();

    float c[16][4];
    #pragma unroll
    for (int t = 0; t < 16; t++)
        c[t][0] = c[t][1] = c[t][2] = c[t][3] = 0.f;

    stage_a(smem + SH_AHI, smem + SH_ALO, g_h + (size_t)row0 * 128, rv, tid);
    __syncthreads();
    mma_phase(c, smem + SH_AHI, smem + SH_ALO, smem + SG_W1H, smem + SG_W1L,
              wband, g, tig);

    epilogue(c, smem, g_h, out, row0, wband, g, tig, n);
}

// ---------------- launch ----------------
extern "C" void kernel_launch(void* const* d_in, const int* in_sizes, int n_in,
                              void* d_out, int out_size) {
    const float* x     = (const float*)d_in[0];
    const int*   ei    = (const int*)d_in[1];
    const float* ew    = (const float*)d_in[2];
    const float* Wrel  = (const float*)d_in[3];
    const float* brel  = (const float*)d_in[4];
    const float* Wroot = (const float*)d_in[5];
    const float* linW  = (const float*)d_in[6];
    const float* linb  = (const float*)d_in[7];
    const float* gamma = (const float*)d_in[8];
    const float* beta  = (const float*)d_in[9];
    float* out = (float*)d_out;

    int n = in_sizes[0] / D;
    int e = in_sizes[2];
    int nsb = (n + 1023) / 1024;

    static bool init_done = false;
    static cudaStream_t s2;
    static cudaEvent_t evF, evX, evA, evJ;
    if (!init_done) {
        cudaStreamCreateWithFlags(&s2, cudaStreamNonBlocking);
        cudaEventCreateWithFlags(&evF, cudaEventDisableTiming);
        cudaEventCreateWithFlags(&evX, cudaEventDisableTiming);
        cudaEventCreateWithFlags(&evA, cudaEventDisableTiming);
        cudaEventCreateWithFlags(&evJ, cudaEventDisableTiming);
        cudaFuncSetAttribute(k_xroot,     cudaFuncAttributeMaxDynamicSharedMemorySize, SMEM_GEMM);
        cudaFuncSetAttribute(k_gemm1_mma, cudaFuncAttributeMaxDynamicSharedMemorySize, SMEM_GEMM);
        cudaFuncSetAttribute(k_gemm2_mma, cudaFuncAttributeMaxDynamicSharedMemorySize, SMEM_GEMM);
        init_done = true;
    }

    // node-half split, rounded to 64-row chunks
    int nchunks = (n + 63) / 64;
    int chA = (nchunks + 1) / 2;
    int rowsA = chA * 64; if (rowsA > n) rowsA = n;
    int chB = (n - rowsA + 63) / 64;

    // ---- fork: side stream does x@Wroot^T + ew tail copy, then gemm1_A ----
    cudaEventRecord(evF, 0);
    cudaStreamWaitEvent(s2, evF, 0);
    k_xroot<<<nchunks, 128, SMEM_GEMM, s2>>>(x, Wroot, n);
    if (out_size >= n * D + e)
        cudaMemcpyAsync(out + (size_t)n * D, ew, (size_t)e * sizeof(float),
                        cudaMemcpyDeviceToDevice, s2);
    cudaEventRecord(evX, s2);

    // ---- main: scatter pipeline, agg in two halves ----
    k_prep<<<(n + 255) / 256, 256>>>(ei, n);
    k_count<<<(e + 255) / 256, 256>>>(ei, e);
    k_scan1<<<nsb, 1024>>>(n);
    k_scan2<<<nsb, 1024>>>(n);
    k_place<<<(e + 255) / 256, 256>>>(ei, ew, e);
    k_agg<<<(rowsA + 7) / 8, 256>>>(x, 0, rowsA);
    cudaEventRecord(evA, 0);
    if (n > rowsA)
        k_agg<<<(n - rowsA + 7) / 8, 256>>>(x, rowsA, n);

    // side: gemm1 on half A overlapping agg half B
    cudaStreamWaitEvent(s2, evA, 0);
    k_gemm1_mma<<<chA, 128, SMEM_GEMM, s2>>>(x, Wrel, brel, gamma, beta, 0, n);
    cudaEventRecord(evJ, s2);

    // main: gemm1 on half B (needs xw), then join, then gemm2
    cudaStreamWaitEvent(0, evX, 0);
    if (chB > 0)
        k_gemm1_mma<<<chB, 128, SMEM_GEMM>>>(x, Wrel, brel, gamma, beta, rowsA, n);
    cudaStreamWaitEvent(0, evJ, 0);
    k_gemm2_mma<<<nchunks, 128, SMEM_GEMM>>>(linW, linb, gamma, beta, out, n);
}